// round 14
// baseline (speedup 1.0000x reference)
#include <cuda_runtime.h>
#include <cstdint>

#define Bz   32
#define Hd   512
#define Tt   1000
#define G4   2048
#define NBLK 128
#define JPB  4          // hidden units per block (16 gate rows)
#define NTHR 256        // 8 warps
#define NW   8
#define KCH  64         // K per warp slice (512 / 8)
#define PS   40         // part row stride (floats): conflict-free reduce
#define NCTR 8          // one counter per contiguous 16-block producer group
#define PER_RUN 16016ull  // per-counter increment per launch: 16 blocks * (1+Tt)

// h broadcast buffer, transposed [k][b], double buffered by step parity.
__device__ float g_hbuf[2][Hd][Bz];
// 8 monotone u64 arrival counters, 128B apart (distinct L2 lines/slices).
// Counter g <- arrivals from blocks [16g, 16g+16) = producers of h rows [64g, 64g+64).
__device__ __align__(128) unsigned long long g_ctr[NCTR * 16];

__device__ __forceinline__ unsigned long long ld_acquire_u64(const unsigned long long* p) {
    unsigned long long v;
    asm volatile("ld.acquire.gpu.global.u64 %0, [%1];" : "=l"(v) : "l"(p) : "memory");
    return v;
}
__device__ __forceinline__ void red_add_release_u64(unsigned long long* p) {
    asm volatile("red.add.release.gpu.global.u64 [%0], %1;" :: "l"(p), "l"(1ull) : "memory");
}

#define FFMA2(d, a, b) asm("fma.rn.f32x2 %0, %1, %2, %0;" : "+l"(d) : "l"(a), "l"(b))

__device__ __forceinline__ float sigf(float x) {
    return __fdividef(1.0f, 1.0f + __expf(-x));
}
__device__ __forceinline__ float tanhf_fast(float x) {
    float e = __expf(2.0f * x);
    return 1.0f - __fdividef(2.0f, e + 1.0f);
}

__global__ void __launch_bounds__(NTHR, 1)
lstm_persistent(const float* __restrict__ wx, const float* __restrict__ u,
                const float* __restrict__ ub, const float* __restrict__ h0,
                const float* __restrict__ c0, float* __restrict__ out)
{
    extern __shared__ float sm[];
    float* u_dup = sm;                     // [512][32]: row r dup at 2r,2r+1   (64KB)
    float* h_shT = u_dup + Hd * 32;        // [512][32]: current h transposed   (64KB)
    float* part  = h_shT + Hd * Bz;        // [8][16*PS]: per-warp partials     (20KB)
    __shared__ unsigned long long s_base[NCTR];

    const int tid  = threadIdx.x;
    const int blk  = blockIdx.x;
    const int j0   = blk * JPB;
    const int lane = tid & 31;

    // per-counter run baseline: exact multiple of PER_RUN (same-run extras <= 16)
    if (tid < NCTR) {
        unsigned long long v = g_ctr[tid * 16];
        s_base[tid] = (v / PER_RUN) * PER_RUN;
    }

    // ---------------- prologue -------------------------------------------------
    // persistent weights, duplicated along r for direct FFMA2 broadcast pairs
    for (int idx = tid; idx < 16 * Hd; idx += NTHR) {
        int r = idx >> 9;                  // local row 0..15
        int k = idx & (Hd - 1);
        int R = ((r >> 2) << 9) + j0 + (r & 3);
        float v = u[(size_t)R * Hd + k];
        u_dup[k * 32 + 2 * r]     = v;
        u_dup[k * 32 + 2 * r + 1] = v;
    }

    const int jj = tid & 3;                // cell-thread coords (tid < 128)
    const int bb = tid >> 2;
    float c_reg = 0.0f, br0 = 0, br1 = 0, br2 = 0, br3 = 0;
    if (tid < 128) {
        c_reg = c0[(size_t)bb * Hd + j0 + jj];
        br0 = __ldg(&ub[0 * Hd + j0 + jj]);
        br1 = __ldg(&ub[1 * Hd + j0 + jj]);
        br2 = __ldg(&ub[2 * Hd + j0 + jj]);
        br3 = __ldg(&ub[3 * Hd + j0 + jj]);
        g_hbuf[0][j0 + jj][bb] = h0[(size_t)bb * Hd + j0 + jj];
    }
    __syncthreads();                       // h0 stores + s_base visible block-wide
    if (tid == 0) red_add_release_u64(&g_ctr[(blk >> 4) * 16]);

    // GEMM tiling: 8 warps = 8 k-slices of 64; per-warp 32 tiles of 4b x 4r
    const int ks = tid >> 5;
    const int bt = lane & 7;               // batches 4*bt..4*bt+3
    const int rt = lane >> 3;              // rows    4*rt..4*rt+3
    const int k0 = ks * KCH;

    // this warp's wait target on ITS producer group's counter
    const unsigned long long* my_ctr = &g_ctr[ks * 16];
    unsigned long long target = s_base[ks] + 16ull;   // group ks prologue done

    const float* hP = h_shT + (size_t)k0 * 32 + bt * 4;
    const float* uP = u_dup + (size_t)k0 * 32 + rt * 8;

    const size_t S = (size_t)Bz * Tt * Hd;

    for (int t = 0; t < Tt; t++) {
        const int p = t & 1;

        // wx prefetch for this step (cell threads), overlaps the wait below
        float wr0 = 0, wr1 = 0, wr2 = 0, wr3 = 0;
        if (tid < 128) {
            const float* wp = wx + ((size_t)bb * Tt + t) * G4 + j0 + jj;
            wr0 = __ldg(wp + 0 * Hd);
            wr1 = __ldg(wp + 1 * Hd);
            wr2 = __ldg(wp + 2 * Hd);
            wr3 = __ldg(wp + 3 * Hd);
        }

        // ---- per-warp wait: only THIS warp's 16 producer blocks ----
        for (;;) {
            unsigned long long v = ld_acquire_u64(my_ctr);  // 1 request/warp/iter
            if ((long long)(v - target) >= 0) break;
        }
        target += 16ull;

        // ---- per-warp h chunk copy: warp ks owns k in [k0, k0+64) ----
        {
            const float4* src = reinterpret_cast<const float4*>(&g_hbuf[p][k0][0]);
            float4*       dst = reinterpret_cast<float4*>(h_shT + k0 * Bz);
            #pragma unroll
            for (int i = 0; i < 16; i++)
                dst[lane + 32 * i] = __ldcg(src + lane + 32 * i);
        }
        __syncwarp();

        // ---- GEMM (FFMA2, duplicated-u layout: 3 LDS + 8 FFMA2 per k) ----
        unsigned long long a00 = 0, a01 = 0, a02 = 0, a03 = 0;
        unsigned long long a10 = 0, a11 = 0, a12 = 0, a13 = 0;
        #pragma unroll 8
        for (int k = 0; k < KCH; k++) {
            ulonglong2 hp  = *reinterpret_cast<const ulonglong2*>(hP + k * 32);
            ulonglong2 ua  = *reinterpret_cast<const ulonglong2*>(uP + k * 32);
            ulonglong2 ub2 = *reinterpret_cast<const ulonglong2*>(uP + k * 32 + 4);
            FFMA2(a00, hp.x, ua.x);  FFMA2(a10, hp.y, ua.x);
            FFMA2(a01, hp.x, ua.y);  FFMA2(a11, hp.y, ua.y);
            FFMA2(a02, hp.x, ub2.x); FFMA2(a12, hp.y, ub2.x);
            FFMA2(a03, hp.x, ub2.y); FFMA2(a13, hp.y, ub2.y);
        }
        {
            unsigned long long* pp = reinterpret_cast<unsigned long long*>(
                part + ks * (16 * PS) + (rt * 4) * PS + bt * 4);
            pp[0]            = a00;  pp[1]            = a10;
            pp[PS / 2]       = a01;  pp[PS / 2 + 1]   = a11;
            pp[PS]           = a02;  pp[PS + 1]       = a12;
            pp[3 * PS / 2]   = a03;  pp[3 * PS / 2+1] = a13;
        }
        __syncthreads();                       // all partials in smem

        // ---- fused reduce + LSTM cell (threads 0..127) ----
        float h, c, it, ft, gt, ot;
        if (tid < 128) {
            float s0, s1, s2, s3;
            {
                const float* pp = part + jj * PS + bb;
                #define RED(g, bias, wxr, dst)                                  \
                {   const float* q = pp + (g) * 4 * PS;                          \
                    float t0 = q[0 * 16 * PS] + q[1 * 16 * PS];                  \
                    float t1 = q[2 * 16 * PS] + q[3 * 16 * PS];                  \
                    float t2 = q[4 * 16 * PS] + q[5 * 16 * PS];                  \
                    float t3 = q[6 * 16 * PS] + q[7 * 16 * PS];                  \
                    dst = (wxr + bias) + ((t0 + t1) + (t2 + t3)); }
                RED(0, br0, wr0, s0)
                RED(1, br1, wr1, s1)
                RED(2, br2, wr2, s2)
                RED(3, br3, wr3, s3)
                #undef RED
            }
            it = sigf(s0);
            ft = sigf(s1);
            gt = tanhf_fast(s2);
            ot = sigf(s3);
            c  = ft * c_reg + it * gt;
            h  = ot * tanhf_fast(c);
            c_reg = c;
            g_hbuf[p ^ 1][j0 + jj][bb] = h;   // weak store; bar.sync + release-red orders it
        }
        __syncthreads();
        if (tid == 0) red_add_release_u64(&g_ctr[(blk >> 4) * 16]);

        if (tid < 128) {                      // outputs off the critical path
            size_t base = ((size_t)bb * Tt + t) * Hd + j0 + jj;
            out[base]         = h;
            out[S + base]     = c;
            out[2 * S + base] = it;
            out[3 * S + base] = ft;
            out[4 * S + base] = gt;
            out[5 * S + base] = ot;
        }
    }
}

extern "C" void kernel_launch(void* const* d_in, const int* in_sizes, int n_in,
                              void* d_out, int out_size) {
    const float* wx = (const float*)d_in[0];
    const float* u  = (const float*)d_in[1];
    const float* ub = (const float*)d_in[2];
    const float* h0 = (const float*)d_in[3];
    const float* c0 = (const float*)d_in[4];
    float* out = (float*)d_out;

    size_t smem = (size_t)(Hd * 32 + Hd * Bz + NW * 16 * PS) * sizeof(float); // 151552 B
    cudaFuncSetAttribute(lstm_persistent,
                         cudaFuncAttributeMaxDynamicSharedMemorySize, (int)smem);
    lstm_persistent<<<NBLK, NTHR, smem>>>(wx, u, ub, h0, c0, out);
}

// round 15
// speedup vs baseline: 1.2850x; 1.2850x over previous
#include <cuda_runtime.h>
#include <cstdint>

#define Bz    32
#define Hd    512
#define Tt    1000
#define G4    2048
#define NBLK  128
#define NTHR  256         // 8 warps
#define NW    8
#define KCH   64          // K per warp slice (512 / 8)
#define US    68          // u_sh row stride (floats): 16B-aligned float4, low conflicts
#define PS2   14          // part row stride (floats): conflict-free reduce, u64-aligned
#define NCTR2 32          // counters: (bg, k-slice-group-of-4-rg-blocks)
#define PER_RUN 4004ull   // per-counter: 4 blocks * (1 + Tt)

// h exchange: [parity][batch-group][k][8 batches] — consumer chunks are dense 2KB.
__device__ float g_hbuf2[2][4][Hd][8];
// 32 monotone u64 arrival counters, 128B apart.
// Counter bg*8+g <- arrivals from blocks (bg, 4g..4g+4) = producers of k rows [64g,64g+64).
__device__ __align__(128) unsigned long long g_ctr[NCTR2 * 16];

__device__ __forceinline__ unsigned long long ld_acquire_u64(const unsigned long long* p) {
    unsigned long long v;
    asm volatile("ld.acquire.gpu.global.u64 %0, [%1];" : "=l"(v) : "l"(p) : "memory");
    return v;
}
__device__ __forceinline__ void red_add_release_u64(unsigned long long* p) {
    asm volatile("red.add.release.gpu.global.u64 [%0], %1;" :: "l"(p), "l"(1ull) : "memory");
}

#define FFMA2(d, a, b) asm("fma.rn.f32x2 %0, %1, %2, %0;" : "+l"(d) : "l"(a), "l"(b))
#define DUP2(d, x) asm("mov.b64 %0, {%1, %1};" : "=l"(d) : "r"(__float_as_uint(x)))

__device__ __forceinline__ float sigf(float x) {
    return __fdividef(1.0f, 1.0f + __expf(-x));
}
__device__ __forceinline__ float tanhf_fast(float x) {
    float e = __expf(2.0f * x);
    return 1.0f - __fdividef(2.0f, e + 1.0f);
}

__global__ void __launch_bounds__(NTHR, 1)
lstm_persistent(const float* __restrict__ wx, const float* __restrict__ u,
                const float* __restrict__ ub, const float* __restrict__ h0,
                const float* __restrict__ c0, float* __restrict__ out)
{
    extern __shared__ float sm[];
    float* u_sh = sm;                      // [512][US]: 64 gate rows (local r = g*16+uu)
    float* h_st = u_sh + Hd * US;          // [512][8]:  this bg's h, dense
    float* part = h_st + Hd * 8;           // [8][64*PS2]: per-warp partials
    __shared__ unsigned long long s_base[NCTR2];

    const int tid  = threadIdx.x;
    const int blk  = blockIdx.x;
    const int BG   = blk >> 5;             // batch group 0..3 (batches 8*BG..8*BG+8)
    const int RG   = blk & 31;             // unit group 0..31 (units 16*RG..16*RG+16)
    const int lane = tid & 31;

    if (tid < NCTR2) {
        unsigned long long v = g_ctr[tid * 16];   // same-run extras <= 4 < PER_RUN
        s_base[tid] = (v / PER_RUN) * PER_RUN;
    }

    // ---------------- prologue: weights (64 rows x 512 k, transposed) -----------
    for (int idx = tid; idx < 64 * Hd; idx += NTHR) {
        int r = idx >> 9;                  // local row 0..63  (g = r>>4, uu = r&15)
        int k = idx & (Hd - 1);
        int R = ((r >> 4) << 9) + RG * 16 + (r & 15);
        u_sh[k * US + r] = u[(size_t)R * Hd + k];
    }

    const int uu = tid & 15;               // cell-thread coords (tid < 128)
    const int bb = tid >> 4;               // batch 0..7 within group
    float c_reg = 0.0f, br0 = 0, br1 = 0, br2 = 0, br3 = 0;
    if (tid < 128) {
        int b  = BG * 8 + bb;
        int jj = RG * 16 + uu;
        c_reg = c0[(size_t)b * Hd + jj];
        br0 = __ldg(&ub[0 * Hd + jj]);
        br1 = __ldg(&ub[1 * Hd + jj]);
        br2 = __ldg(&ub[2 * Hd + jj]);
        br3 = __ldg(&ub[3 * Hd + jj]);
        g_hbuf2[0][BG][jj][bb] = h0[(size_t)b * Hd + jj];
    }
    __syncthreads();                       // h0 stores + s_base visible
    if (tid == 0) red_add_release_u64(&g_ctr[(BG * 8 + (RG >> 2)) * 16]);

    // GEMM tiling: 8 warps = 8 k-slices of 64; lane = bt*16 + rt
    const int ks = tid >> 5;
    const int rt = lane & 15;              // rows    4*rt..4*rt+4
    const int bt = lane >> 4;              // batches 4*bt..4*bt+4 (2 f32x2 pairs)
    const int k0 = ks * KCH;

    const unsigned long long* my_ctr = &g_ctr[(BG * 8 + ks) * 16];
    unsigned long long target = s_base[BG * 8 + ks] + 4ull;

    const float* hP = h_st + (size_t)k0 * 8 + bt * 4;
    const float* uP = u_sh + (size_t)k0 * US + rt * 4;

    const size_t S = (size_t)Bz * Tt * Hd;

    for (int t = 0; t < Tt; t++) {
        const int p = t & 1;

        // wx prefetch (cell threads), overlaps the wait below
        float wr0 = 0, wr1 = 0, wr2 = 0, wr3 = 0;
        if (tid < 128) {
            const float* wp = wx + ((size_t)(BG * 8 + bb) * Tt + t) * G4 + RG * 16 + uu;
            wr0 = __ldg(wp + 0 * Hd);
            wr1 = __ldg(wp + 1 * Hd);
            wr2 = __ldg(wp + 2 * Hd);
            wr3 = __ldg(wp + 3 * Hd);
        }

        // ---- per-warp wait: only THIS warp's 4 producer blocks ----
        for (;;) {
            unsigned long long v = ld_acquire_u64(my_ctr);
            if ((long long)(v - target) >= 0) break;
        }
        target += 4ull;

        // ---- per-warp h chunk copy: dense 2KB (64 k x 8 batches) ----
        {
            const unsigned long long* src =
                reinterpret_cast<const unsigned long long*>(&g_hbuf2[p][BG][k0][0]);
            unsigned long long* dst =
                reinterpret_cast<unsigned long long*>(h_st + k0 * 8);
            #pragma unroll
            for (int i = 0; i < 8; i++) {
                unsigned long long v;
                asm volatile("ld.global.cg.b64 %0, [%1];" : "=l"(v)
                             : "l"(src + lane + 32 * i) : "memory");
                dst[lane + 32 * i] = v;
            }
        }
        __syncwarp();

        // ---- GEMM: per k: 2 LDS.128 + 4 DUP2 + 8 FFMA2 (R9 shape) ----
        unsigned long long a00 = 0, a01 = 0, a10 = 0, a11 = 0;
        unsigned long long a20 = 0, a21 = 0, a30 = 0, a31 = 0;
        #pragma unroll 8
        for (int k = 0; k < KCH; k++) {
            ulonglong2 hp = *reinterpret_cast<const ulonglong2*>(hP + k * 8);
            float4     uv = *reinterpret_cast<const float4*>(uP + k * US);
            unsigned long long u0, u1, u2, u3;
            DUP2(u0, uv.x); DUP2(u1, uv.y); DUP2(u2, uv.z); DUP2(u3, uv.w);
            FFMA2(a00, hp.x, u0); FFMA2(a01, hp.y, u0);
            FFMA2(a10, hp.x, u1); FFMA2(a11, hp.y, u1);
            FFMA2(a20, hp.x, u2); FFMA2(a21, hp.y, u2);
            FFMA2(a30, hp.x, u3); FFMA2(a31, hp.y, u3);
        }
        {
            // part[ks][r][b]: r stride PS2(=14, even -> u64 aligned)
            unsigned long long* pp = reinterpret_cast<unsigned long long*>(
                part + ks * (64 * PS2) + (rt * 4) * PS2 + bt * 4);
            pp[0]              = a00;  pp[1]              = a01;
            pp[PS2 / 2]        = a10;  pp[PS2 / 2 + 1]    = a11;
            pp[PS2]            = a20;  pp[PS2 + 1]        = a21;
            pp[3 * PS2 / 2]    = a30;  pp[3 * PS2 / 2 + 1] = a31;
        }
        __syncthreads();                   // all partials in smem

        // ---- fused reduce + LSTM cell (threads 0..127) ----
        float h, c, it, ft, gt, ot;
        if (tid < 128) {
            float s0, s1, s2, s3;
            {
                const float* q0 = part + uu * PS2 + bb;   // gate g adds g*16*PS2
                #define RED(g, bias, wxr, dst)                                   \
                {   const float* q = q0 + (g) * 16 * PS2;                         \
                    float t0 = q[0 * 64 * PS2] + q[1 * 64 * PS2];                 \
                    float t1 = q[2 * 64 * PS2] + q[3 * 64 * PS2];                 \
                    float t2 = q[4 * 64 * PS2] + q[5 * 64 * PS2];                 \
                    float t3 = q[6 * 64 * PS2] + q[7 * 64 * PS2];                 \
                    dst = (wxr + bias) + ((t0 + t1) + (t2 + t3)); }
                RED(0, br0, wr0, s0)
                RED(1, br1, wr1, s1)
                RED(2, br2, wr2, s2)
                RED(3, br3, wr3, s3)
                #undef RED
            }
            it = sigf(s0);
            ft = sigf(s1);
            gt = tanhf_fast(s2);
            ot = sigf(s3);
            c  = ft * c_reg + it * gt;
            h  = ot * tanhf_fast(c);
            c_reg = c;
            g_hbuf2[p ^ 1][BG][RG * 16 + uu][bb] = h;  // weak; bar + release orders it
        }
        __syncthreads();
        if (tid == 0) red_add_release_u64(&g_ctr[(BG * 8 + (RG >> 2)) * 16]);

        if (tid < 128) {                   // outputs off the critical path
            size_t base = ((size_t)(BG * 8 + bb) * Tt + t) * Hd + RG * 16 + uu;
            out[base]         = h;
            out[S + base]     = c;
            out[2 * S + base] = it;
            out[3 * S + base] = ft;
            out[4 * S + base] = gt;
            out[5 * S + base] = ot;
        }
    }
}

extern "C" void kernel_launch(void* const* d_in, const int* in_sizes, int n_in,
                              void* d_out, int out_size) {
    const float* wx = (const float*)d_in[0];
    const float* u  = (const float*)d_in[1];
    const float* ub = (const float*)d_in[2];
    const float* h0 = (const float*)d_in[3];
    const float* c0 = (const float*)d_in[4];
    float* out = (float*)d_out;

    size_t smem = (size_t)(Hd * US + Hd * 8 + NW * 64 * PS2) * sizeof(float); // 184320 B
    cudaFuncSetAttribute(lstm_persistent,
                         cudaFuncAttributeMaxDynamicSharedMemorySize, (int)smem);
    lstm_persistent<<<NBLK, NTHR, smem>>>(wx, u, ub, h0, c0, out);
}